// round 1
// baseline (speedup 1.0000x reference)
#include <cuda_runtime.h>
#include <math.h>

#define Bb 4
#define Ss 2048
#define Hh 768
#define NH 12
#define HD 64

// Scratch (allocation-free rule: __device__ globals)
// g_qkv layout: [which(3)][b][head][s][d]
__device__ float g_qkv[3 * Bb * NH * Ss * HD];   // 18,874,368 floats
// g_ctx layout: [b][s][h] (h = head*64 + d)
__device__ float g_ctx[Bb * Ss * Hh];            //  6,291,456 floats

// ---------------------------------------------------------------------------
// Generic 64x64 tiled GEMM, 256 threads, 4x4 microtile, BK=16.
// MODE 1: A = x (param), epilogue scatters into g_qkv (QKV projection)
// MODE 2: A = g_ctx (ignores A param), plain epilogue into C (out projection)
// ---------------------------------------------------------------------------
template <int MODE>
__global__ void __launch_bounds__(256)
gemm64(const float* __restrict__ A, const float* __restrict__ Bm,
       float* __restrict__ C, int M, int N, int K)
{
    __shared__ float As[16][68];   // transposed: As[k][m], padded
    __shared__ float Bs[16][64];   // Bs[k][n]

    const int t  = threadIdx.x;
    const int m0 = blockIdx.y * 64;
    const int n0 = blockIdx.x * 64;
    const int ty = t >> 4, tx = t & 15;

    const int arow = t >> 2, aq = (t & 3) << 2;    // A loader: row, k-quad
    const int brow = t >> 4, bq = (t & 15) << 2;   // B loader: k-row, n-quad

    const float* Ap = (MODE == 2) ? (const float*)g_ctx : A;
    const float* Aptr = Ap + (size_t)(m0 + arow) * K + aq;
    const float* Bptr = Bm + (size_t)brow * N + (n0 + bq);

    float acc[4][4] = {};

    float4 av = *(const float4*)(Aptr);
    float4 bv = *(const float4*)(Bptr);

    for (int k0 = 0; k0 < K; k0 += 16) {
        As[aq + 0][arow] = av.x;
        As[aq + 1][arow] = av.y;
        As[aq + 2][arow] = av.z;
        As[aq + 3][arow] = av.w;
        *(float4*)&Bs[brow][bq] = bv;
        __syncthreads();

        if (k0 + 16 < K) {   // prefetch next tile into regs during compute
            av = *(const float4*)(Aptr + k0 + 16);
            bv = *(const float4*)(Bptr + (size_t)(k0 + 16) * N);
        }

        #pragma unroll
        for (int kk = 0; kk < 16; kk++) {
            float4 a = *(const float4*)&As[kk][ty << 2];
            float4 b = *(const float4*)&Bs[kk][tx << 2];
            float ar[4] = {a.x, a.y, a.z, a.w};
            float br[4] = {b.x, b.y, b.z, b.w};
            #pragma unroll
            for (int i = 0; i < 4; i++)
                #pragma unroll
                for (int j = 0; j < 4; j++)
                    acc[i][j] += ar[i] * br[j];
        }
        __syncthreads();
    }

    #pragma unroll
    for (int i = 0; i < 4; i++) {
        const int row  = m0 + (ty << 2) + i;
        const int col0 = n0 + (tx << 2);
        float4 v = make_float4(acc[i][0], acc[i][1], acc[i][2], acc[i][3]);
        if (MODE == 1) {
            const int which = col0 / Hh;
            const int rem   = col0 - which * Hh;
            const int head  = rem >> 6;
            const int d0    = rem & 63;
            const int bb    = row >> 11;          // row / 2048
            const int ss    = row & (Ss - 1);
            const size_t off =
                ((((size_t)which * Bb + bb) * NH + head) * Ss + ss) * HD + d0;
            *(float4*)(g_qkv + off) = v;
        } else {
            *(float4*)(C + (size_t)row * N + col0) = v;
        }
    }
}

// ---------------------------------------------------------------------------
// Flash attention (fp32, causal). One block per (b, head, 64-row q tile).
// 256 threads: thread (ty,tx) owns q-rows ty*4..+3 and key/d cols tx*4..+3.
// Row-group = 16 contiguous lanes (same ty) -> butterfly reductions st=1,2,4,8.
// ---------------------------------------------------------------------------
__global__ void __launch_bounds__(256)
attn_kernel()
{
    extern __shared__ float sm[];
    float* Qs = sm;                 // [64][68]  Qs[d*68 + row]   (transposed)
    float* Ks = sm + 64 * 68;       // [64][68]  Ks[d*68 + col]   (transposed)
    float* Ps = sm + 2 * 64 * 68;   // [64][68]  Ps[key*68 + row] (transposed)
    float* Vs = sm + 3 * 64 * 68;   // [64][64]  Vs[key*64 + d]

    const int t  = threadIdx.x;
    const int iq = blockIdx.x;      // q tile (32 tiles of 64 rows)
    const int h  = blockIdx.y;
    const int b  = blockIdx.z;
    const int ty = t >> 4, tx = t & 15;

    const size_t head_off = (((size_t)b * NH) + h) * (size_t)Ss * HD;
    const size_t plane    = (size_t)Bb * NH * Ss * HD;
    const float* Qg = g_qkv + 0 * plane + head_off + (size_t)iq * 64 * HD;
    const float* Kg = g_qkv + 1 * plane + head_off;
    const float* Vg = g_qkv + 2 * plane + head_off;

    // Load Q tile, transposed into Qs[d][row]
    #pragma unroll
    for (int it = 0; it < 4; it++) {
        int idx = t + it * 256;
        int row = idx >> 4, quad = idx & 15;
        float4 v = *(const float4*)(Qg + row * HD + quad * 4);
        Qs[(quad * 4 + 0) * 68 + row] = v.x;
        Qs[(quad * 4 + 1) * 68 + row] = v.y;
        Qs[(quad * 4 + 2) * 68 + row] = v.z;
        Qs[(quad * 4 + 3) * 68 + row] = v.w;
    }

    float o[4][4] = {};
    float mi[4] = {-1e30f, -1e30f, -1e30f, -1e30f};
    float li[4] = {0.f, 0.f, 0.f, 0.f};

    for (int jt = 0; jt <= iq; jt++) {
        __syncthreads();   // prior-tile reads of Ks/Vs/Ps complete
        #pragma unroll
        for (int it = 0; it < 4; it++) {
            int idx = t + it * 256;
            int row = idx >> 4, quad = idx & 15;
            float4 kv = *(const float4*)(Kg + (jt * 64 + row) * HD + quad * 4);
            Ks[(quad * 4 + 0) * 68 + row] = kv.x;
            Ks[(quad * 4 + 1) * 68 + row] = kv.y;
            Ks[(quad * 4 + 2) * 68 + row] = kv.z;
            Ks[(quad * 4 + 3) * 68 + row] = kv.w;
            float4 vv = *(const float4*)(Vg + (jt * 64 + row) * HD + quad * 4);
            *(float4*)&Vs[row * 64 + quad * 4] = vv;
        }
        __syncthreads();

        // S = Q @ K^T (64x64x64)
        float s[4][4] = {};
        #pragma unroll 8
        for (int d = 0; d < 64; d++) {
            float4 a  = *(const float4*)&Qs[d * 68 + (ty << 2)];
            float4 b4 = *(const float4*)&Ks[d * 68 + (tx << 2)];
            float ar[4] = {a.x, a.y, a.z, a.w};
            float br[4] = {b4.x, b4.y, b4.z, b4.w};
            #pragma unroll
            for (int i = 0; i < 4; i++)
                #pragma unroll
                for (int j = 0; j < 4; j++)
                    s[i][j] += ar[i] * br[j];
        }

        // scale + causal mask (diagonal tile only)
        #pragma unroll
        for (int i = 0; i < 4; i++)
            #pragma unroll
            for (int j = 0; j < 4; j++)
                s[i][j] *= 0.125f;                 // 1/sqrt(64)
        if (jt == iq) {
            #pragma unroll
            for (int i = 0; i < 4; i++)
                #pragma unroll
                for (int j = 0; j < 4; j++)
                    if ((tx << 2) + j > (ty << 2) + i) s[i][j] = -1e30f;
        }

        // online softmax update (per q-row, across the 16-lane row group)
        #pragma unroll
        for (int i = 0; i < 4; i++) {
            float mt = fmaxf(fmaxf(s[i][0], s[i][1]), fmaxf(s[i][2], s[i][3]));
            #pragma unroll
            for (int st = 1; st < 16; st <<= 1)
                mt = fmaxf(mt, __shfl_xor_sync(0xffffffffu, mt, st));
            float mn = fmaxf(mi[i], mt);
            float f  = __expf(mi[i] - mn);
            float rs = 0.f;
            #pragma unroll
            for (int j = 0; j < 4; j++) {
                s[i][j] = __expf(s[i][j] - mn);
                rs += s[i][j];
            }
            #pragma unroll
            for (int st = 1; st < 16; st <<= 1)
                rs += __shfl_xor_sync(0xffffffffu, rs, st);
            li[i] = li[i] * f + rs;
            mi[i] = mn;
            #pragma unroll
            for (int j = 0; j < 4; j++) o[i][j] *= f;
        }

        // stage P transposed: Ps[key][row]
        #pragma unroll
        for (int i = 0; i < 4; i++)
            #pragma unroll
            for (int j = 0; j < 4; j++)
                Ps[((tx << 2) + j) * 68 + (ty << 2) + i] = s[i][j];
        __syncthreads();

        // O += P @ V (64x64x64)
        #pragma unroll 8
        for (int c = 0; c < 64; c++) {
            float4 a  = *(const float4*)&Ps[c * 68 + (ty << 2)];
            float4 b4 = *(const float4*)&Vs[c * 64 + (tx << 2)];
            float ar[4] = {a.x, a.y, a.z, a.w};
            float br[4] = {b4.x, b4.y, b4.z, b4.w};
            #pragma unroll
            for (int i = 0; i < 4; i++)
                #pragma unroll
                for (int j = 0; j < 4; j++)
                    o[i][j] += ar[i] * br[j];
        }
    }

    // normalize + write ctx [b][s][head*64+d]
    #pragma unroll
    for (int i = 0; i < 4; i++) {
        float inv = 1.0f / li[i];
        int row = iq * 64 + (ty << 2) + i;
        float4 v = make_float4(o[i][0] * inv, o[i][1] * inv,
                               o[i][2] * inv, o[i][3] * inv);
        *(float4*)(g_ctx + ((size_t)b * Ss + row) * Hh + h * HD + (tx << 2)) = v;
    }
}

// ---------------------------------------------------------------------------

extern "C" void kernel_launch(void* const* d_in, const int* in_sizes, int n_in,
                              void* d_out, int out_size)
{
    const float* x    = (const float*)d_in[0];   // [4,2048,768]
    const float* wqkv = (const float*)d_in[1];   // [768,2304]
    const float* wout = (const float*)d_in[2];   // [768,768]
    float* out = (float*)d_out;                  // [4,2048,768]

    // 1) QKV projection with head-scatter epilogue
    gemm64<1><<<dim3(2304 / 64, 8192 / 64), 256>>>(x, wqkv, nullptr,
                                                   Bb * Ss, 3 * Hh, Hh);

    // 2) Flash attention (causal), dynamic smem 68608 B
    const int SMEM = (3 * 64 * 68 + 64 * 64) * (int)sizeof(float);
    cudaFuncSetAttribute(attn_kernel,
                         cudaFuncAttributeMaxDynamicSharedMemorySize, SMEM);
    attn_kernel<<<dim3(Ss / 64, NH, Bb), 256, SMEM>>>();

    // 3) Output projection
    gemm64<2><<<dim3(768 / 64, 8192 / 64), 256>>>(nullptr, wout, out,
                                                  Bb * Ss, Hh, Hh);
}

// round 2
// speedup vs baseline: 1.2357x; 1.2357x over previous
#include <cuda_runtime.h>
#include <math.h>

#define Bb 4
#define Ss 2048
#define Hh 768
#define NH 12
#define HD 64

// Scratch (allocation-free rule: __device__ globals)
__device__ float g_qkv[3 * Bb * NH * Ss * HD];   // [which][b][head][s][d]
__device__ float g_ctx[Bb * Ss * Hh];            // [b][s][h]

// ---------------------------------------------------------------------------
// 128x128 tiled fp32 GEMM, 256 threads, 8x8 microtile, BK=16.
// MODE 1: A = x, epilogue scatters into g_qkv (QKV projection)
// MODE 2: A = g_ctx, plain epilogue into C (out projection)
// ---------------------------------------------------------------------------
template <int MODE>
__global__ void __launch_bounds__(256)
gemm128(const float* __restrict__ A, const float* __restrict__ Bm,
        float* __restrict__ C, int M, int N, int K)
{
    __shared__ float As[16][132];   // As[k][m], padded
    __shared__ float Bs[16][128];   // Bs[k][n]

    const int t  = threadIdx.x;
    const int m0 = blockIdx.y * 128;
    const int n0 = blockIdx.x * 128;
    const int tr = t >> 4, tc = t & 15;

    const int arow = t >> 2, aq = (t & 3) << 2;    // A loader
    const int brow = t >> 4, bcol = (t & 15) << 3; // B loader

    const float* Ap = (MODE == 2) ? (const float*)g_ctx : A;
    const float* Aptr  = Ap + (size_t)(m0 + arow) * K + aq;
    const float* Aptr2 = Aptr + (size_t)64 * K;
    const float* Bptr  = Bm + (size_t)brow * N + (n0 + bcol);

    float acc[8][8] = {};

    float4 av0 = *(const float4*)(Aptr);
    float4 av1 = *(const float4*)(Aptr2);
    float4 bv0 = *(const float4*)(Bptr);
    float4 bv1 = *(const float4*)(Bptr + 4);

    for (int k0 = 0; k0 < K; k0 += 16) {
        As[aq + 0][arow] = av0.x;  As[aq + 1][arow] = av0.y;
        As[aq + 2][arow] = av0.z;  As[aq + 3][arow] = av0.w;
        As[aq + 0][arow + 64] = av1.x;  As[aq + 1][arow + 64] = av1.y;
        As[aq + 2][arow + 64] = av1.z;  As[aq + 3][arow + 64] = av1.w;
        *(float4*)&Bs[brow][bcol]     = bv0;
        *(float4*)&Bs[brow][bcol + 4] = bv1;
        __syncthreads();

        if (k0 + 16 < K) {   // prefetch next tile into regs during compute
            av0 = *(const float4*)(Aptr  + k0 + 16);
            av1 = *(const float4*)(Aptr2 + k0 + 16);
            bv0 = *(const float4*)(Bptr + (size_t)(k0 + 16) * N);
            bv1 = *(const float4*)(Bptr + (size_t)(k0 + 16) * N + 4);
        }

        #pragma unroll
        for (int kk = 0; kk < 16; kk++) {
            float4 a0 = *(const float4*)&As[kk][tr << 2];
            float4 a1 = *(const float4*)&As[kk][(tr << 2) + 64];
            float4 b0 = *(const float4*)&Bs[kk][tc << 2];
            float4 b1 = *(const float4*)&Bs[kk][(tc << 2) + 64];
            float ar[8] = {a0.x, a0.y, a0.z, a0.w, a1.x, a1.y, a1.z, a1.w};
            float br[8] = {b0.x, b0.y, b0.z, b0.w, b1.x, b1.y, b1.z, b1.w};
            #pragma unroll
            for (int i = 0; i < 8; i++)
                #pragma unroll
                for (int j = 0; j < 8; j++)
                    acc[i][j] += ar[i] * br[j];
        }
        __syncthreads();
    }

    #pragma unroll
    for (int ii = 0; ii < 8; ii++) {
        const int row = m0 + ((ii < 4) ? (tr << 2) + ii : 64 + (tr << 2) + ii - 4);
        #pragma unroll
        for (int jj = 0; jj < 2; jj++) {
            const int col0 = n0 + (tc << 2) + jj * 64;
            float4 v = make_float4(acc[ii][jj * 4 + 0], acc[ii][jj * 4 + 1],
                                   acc[ii][jj * 4 + 2], acc[ii][jj * 4 + 3]);
            if (MODE == 1) {
                const int which = col0 / Hh;
                const int rem   = col0 - which * Hh;
                const int head  = rem >> 6;
                const int d0    = rem & 63;
                const int bb    = row >> 11;
                const int ss    = row & (Ss - 1);
                const size_t off =
                    ((((size_t)which * Bb + bb) * NH + head) * Ss + ss) * HD + d0;
                *(float4*)(g_qkv + off) = v;
            } else {
                *(float4*)(C + (size_t)row * N + col0) = v;
            }
        }
    }
}

// ---------------------------------------------------------------------------
// Flash attention fp32 causal. Q-tile 128 x K-tile 128, 256 threads.
// S-GEMM: 8x8 microtile (1B/FMA). O-GEMM: 8x4 microtile.
// Ps (128x132) overlays the Ks (64x132) buffer.
// ---------------------------------------------------------------------------
__global__ void __launch_bounds__(256)
attn_kernel()
{
    extern __shared__ float sm[];
    float* KP = sm;                    // Ks[d][col] (64x132) then Ps[key][row] (128x132)
    float* Qs = sm + 128 * 132;        // [64][132]  Qs[d][row]
    float* Vs = sm + 128 * 132 + 64 * 132;  // [128][68] Vs[key][d]

    const int t  = threadIdx.x;
    const int iq = blockIdx.x;         // 16 q tiles of 128 rows
    const int h  = blockIdx.y;
    const int b  = blockIdx.z;
    const int ty = t >> 4, tx = t & 15;

    const size_t head_off = (((size_t)b * NH) + h) * (size_t)Ss * HD;
    const size_t plane    = (size_t)Bb * NH * Ss * HD;
    const float* Qg = g_qkv + 0 * plane + head_off + (size_t)iq * 128 * HD;
    const float* Kg = g_qkv + 1 * plane + head_off;
    const float* Vg = g_qkv + 2 * plane + head_off;

    // Load Q tile (128x64), transposed into Qs[d][row]
    #pragma unroll
    for (int it = 0; it < 8; it++) {
        int idx = t + it * 256;
        int row = idx >> 4, quad = idx & 15;
        float4 v = *(const float4*)(Qg + row * HD + quad * 4);
        Qs[(quad * 4 + 0) * 132 + row] = v.x;
        Qs[(quad * 4 + 1) * 132 + row] = v.y;
        Qs[(quad * 4 + 2) * 132 + row] = v.z;
        Qs[(quad * 4 + 3) * 132 + row] = v.w;
    }

    float o[8][4] = {};
    float mi[8], li[8];
    #pragma unroll
    for (int i = 0; i < 8; i++) { mi[i] = -1e30f; li[i] = 0.f; }

    for (int jt = 0; jt <= iq; jt++) {
        __syncthreads();   // prior O-GEMM reads of KP/Vs complete
        // Load K tile transposed into KP as Ks[d][col], V tile into Vs[key][d]
        #pragma unroll
        for (int it = 0; it < 8; it++) {
            int idx = t + it * 256;
            int row = idx >> 4, quad = idx & 15;
            float4 kv = *(const float4*)(Kg + (size_t)(jt * 128 + row) * HD + quad * 4);
            KP[(quad * 4 + 0) * 132 + row] = kv.x;
            KP[(quad * 4 + 1) * 132 + row] = kv.y;
            KP[(quad * 4 + 2) * 132 + row] = kv.z;
            KP[(quad * 4 + 3) * 132 + row] = kv.w;
            float4 vv = *(const float4*)(Vg + (size_t)(jt * 128 + row) * HD + quad * 4);
            *(float4*)&Vs[row * 68 + quad * 4] = vv;
        }
        __syncthreads();

        // S = Q @ K^T  (128x128x64), 8x8 microtile
        float s[8][8] = {};
        #pragma unroll 8
        for (int d = 0; d < 64; d++) {
            float4 a0 = *(const float4*)&Qs[d * 132 + (ty << 2)];
            float4 a1 = *(const float4*)&Qs[d * 132 + 64 + (ty << 2)];
            float4 b0 = *(const float4*)&KP[d * 132 + (tx << 2)];
            float4 b1 = *(const float4*)&KP[d * 132 + 64 + (tx << 2)];
            float ar[8] = {a0.x, a0.y, a0.z, a0.w, a1.x, a1.y, a1.z, a1.w};
            float br[8] = {b0.x, b0.y, b0.z, b0.w, b1.x, b1.y, b1.z, b1.w};
            #pragma unroll
            for (int i = 0; i < 8; i++)
                #pragma unroll
                for (int j = 0; j < 8; j++)
                    s[i][j] += ar[i] * br[j];
        }

        // scale + causal mask (diagonal tile only)
        #pragma unroll
        for (int i = 0; i < 8; i++)
            #pragma unroll
            for (int j = 0; j < 8; j++)
                s[i][j] *= 0.125f;
        if (jt == iq) {
            #pragma unroll
            for (int i = 0; i < 8; i++) {
                int lr = (i < 4) ? (ty << 2) + i : 64 + (ty << 2) + i - 4;
                #pragma unroll
                for (int j = 0; j < 8; j++) {
                    int lc = (j < 4) ? (tx << 2) + j : 64 + (tx << 2) + j - 4;
                    if (lc > lr) s[i][j] = -1e30f;
                }
            }
        }

        // online softmax per q-row (16-lane butterfly across tx group)
        #pragma unroll
        for (int i = 0; i < 8; i++) {
            float mt = s[i][0];
            #pragma unroll
            for (int j = 1; j < 8; j++) mt = fmaxf(mt, s[i][j]);
            #pragma unroll
            for (int st = 1; st < 16; st <<= 1)
                mt = fmaxf(mt, __shfl_xor_sync(0xffffffffu, mt, st));
            float mn = fmaxf(mi[i], mt);
            float f  = __expf(mi[i] - mn);
            float rs = 0.f;
            #pragma unroll
            for (int j = 0; j < 8; j++) {
                s[i][j] = __expf(s[i][j] - mn);
                rs += s[i][j];
            }
            #pragma unroll
            for (int st = 1; st < 16; st <<= 1)
                rs += __shfl_xor_sync(0xffffffffu, rs, st);
            li[i] = li[i] * f + rs;
            mi[i] = mn;
            #pragma unroll
            for (int j = 0; j < 4; j++) o[i][j] *= f;
        }

        __syncthreads();   // all Ks reads done before overwrite with Ps

        // stage P transposed: Ps[key][row] (overlays Ks)
        #pragma unroll
        for (int i = 0; i < 8; i++) {
            int lr = (i < 4) ? (ty << 2) + i : 64 + (ty << 2) + i - 4;
            #pragma unroll
            for (int j = 0; j < 8; j++) {
                int lc = (j < 4) ? (tx << 2) + j : 64 + (tx << 2) + j - 4;
                KP[lc * 132 + lr] = s[i][j];
            }
        }
        __syncthreads();

        // O += P @ V  (128x64x128), 8x4 microtile
        #pragma unroll 4
        for (int c = 0; c < 128; c++) {
            float4 a0 = *(const float4*)&KP[c * 132 + (ty << 2)];
            float4 a1 = *(const float4*)&KP[c * 132 + 64 + (ty << 2)];
            float4 b4 = *(const float4*)&Vs[c * 68 + (tx << 2)];
            float ar[8] = {a0.x, a0.y, a0.z, a0.w, a1.x, a1.y, a1.z, a1.w};
            float br[4] = {b4.x, b4.y, b4.z, b4.w};
            #pragma unroll
            for (int i = 0; i < 8; i++)
                #pragma unroll
                for (int j = 0; j < 4; j++)
                    o[i][j] += ar[i] * br[j];
        }
    }

    // normalize + write ctx [b][s][head*64+d]
    #pragma unroll
    for (int i = 0; i < 8; i++) {
        int lr = (i < 4) ? (ty << 2) + i : 64 + (ty << 2) + i - 4;
        float inv = 1.0f / li[i];
        int row = iq * 128 + lr;
        float4 v = make_float4(o[i][0] * inv, o[i][1] * inv,
                               o[i][2] * inv, o[i][3] * inv);
        *(float4*)(g_ctx + ((size_t)b * Ss + row) * Hh + h * HD + (tx << 2)) = v;
    }
}

// ---------------------------------------------------------------------------

extern "C" void kernel_launch(void* const* d_in, const int* in_sizes, int n_in,
                              void* d_out, int out_size)
{
    const float* x    = (const float*)d_in[0];   // [4,2048,768]
    const float* wqkv = (const float*)d_in[1];   // [768,2304]
    const float* wout = (const float*)d_in[2];   // [768,768]
    float* out = (float*)d_out;                  // [4,2048,768]

    // 1) QKV projection with head-scatter epilogue
    gemm128<1><<<dim3(2304 / 128, 8192 / 128), 256>>>(x, wqkv, nullptr,
                                                      Bb * Ss, 3 * Hh, Hh);

    // 2) Flash attention (causal): smem = (128*132 + 64*132 + 128*68)*4 B
    const int SMEM = (128 * 132 + 64 * 132 + 128 * 68) * (int)sizeof(float);
    cudaFuncSetAttribute(attn_kernel,
                         cudaFuncAttributeMaxDynamicSharedMemorySize, SMEM);
    attn_kernel<<<dim3(Ss / 128, NH, Bb), 256, SMEM>>>();

    // 3) Output projection
    gemm128<2><<<dim3(768 / 128, 8192 / 128), 256>>>(nullptr, wout, out,
                                                     Bb * Ss, Hh, Hh);
}

// round 4
// speedup vs baseline: 2.1327x; 1.7259x over previous
#include <cuda_runtime.h>
#include <cuda_bf16.h>
#include <stdint.h>
#include <math.h>

#define Bb 4
#define Ss 2048
#define Hh 768
#define NH 12
#define HD 64

// Scratch (allocation-free rule: __device__ globals)
__device__ float g_qkv[3 * Bb * NH * Ss * HD];   // [which][b][head][s][d]
__device__ float g_ctx[Bb * Ss * Hh];            // [b][s][h]

// ---------------------------------------------------------------------------
// Helpers: bf16 packing / hi-lo split, ldmatrix, mma
// ---------------------------------------------------------------------------
__device__ __forceinline__ uint32_t packbf(float lo, float hi) {
    // d[31:16] = bf16(first src), d[15:0] = bf16(second src)
    uint32_t r;
    asm("cvt.rn.bf16x2.f32 %0, %1, %2;" : "=r"(r) : "f"(hi), "f"(lo));
    return r;
}
__device__ __forceinline__ float2 unpackbf(uint32_t u) {
    __nv_bfloat162 h = *reinterpret_cast<__nv_bfloat162*>(&u);
    return make_float2(__bfloat162float(h.x), __bfloat162float(h.y));
}
// split (x,y) into hi pair and lo (residual) pair
__device__ __forceinline__ void split2(float x, float y, uint32_t& hi, uint32_t& lo) {
    hi = packbf(x, y);
    float2 h = unpackbf(hi);
    lo = packbf(x - h.x, y - h.y);
}

#define LDSM4(r0, r1, r2, r3, a)                                              \
    asm volatile("ldmatrix.sync.aligned.m8n8.x4.shared.b16 {%0,%1,%2,%3}, [%4];" \
                 : "=r"(r0), "=r"(r1), "=r"(r2), "=r"(r3) : "r"(a))
#define LDSM4T(r0, r1, r2, r3, a)                                             \
    asm volatile("ldmatrix.sync.aligned.m8n8.x4.trans.shared.b16 {%0,%1,%2,%3}, [%4];" \
                 : "=r"(r0), "=r"(r1), "=r"(r2), "=r"(r3) : "r"(a))

__device__ __forceinline__ void mma16816(float* c, const uint32_t* a,
                                         uint32_t b0, uint32_t b1) {
    asm volatile(
        "mma.sync.aligned.m16n8k16.row.col.f32.bf16.bf16.f32 "
        "{%0,%1,%2,%3}, {%4,%5,%6,%7}, {%8,%9}, {%0,%1,%2,%3};"
        : "+f"(c[0]), "+f"(c[1]), "+f"(c[2]), "+f"(c[3])
        : "r"(a[0]), "r"(a[1]), "r"(a[2]), "r"(a[3]), "r"(b0), "r"(b1));
}

__device__ __forceinline__ uint32_t sptr(const void* p) {
    return (uint32_t)__cvta_generic_to_shared(p);
}

// ---------------------------------------------------------------------------
// Projection GEMM: 128x128 CTA tile, BK=32, 8 warps (warp tile 32x64),
// bf16x3: acc += Ahi*Bhi + Ahi*Blo + Alo*Bhi
// MODE 1: A = x, scatter epilogue into g_qkv. MODE 2: A = g_ctx, C out.
// ---------------------------------------------------------------------------
#define ASTR 40    // A smem row stride (halves)
#define BSTR 136   // B smem row stride (halves)

template <int MODE>
__global__ void __launch_bounds__(256)
gemm_mma(const float* __restrict__ A, const float* __restrict__ Bm,
         float* __restrict__ C, int M, int N, int K)
{
    __shared__ __align__(16) __nv_bfloat16 Ahi[128 * ASTR];
    __shared__ __align__(16) __nv_bfloat16 Alo[128 * ASTR];
    __shared__ __align__(16) __nv_bfloat16 Bhi[32 * BSTR];
    __shared__ __align__(16) __nv_bfloat16 Blo[32 * BSTR];

    const int t = threadIdx.x;
    const int lane = t & 31, warp = t >> 5;
    const int m0 = blockIdx.y * 128, n0 = blockIdx.x * 128;
    const int wm = (warp >> 1) * 32, wn = (warp & 1) * 64;

    // loaders: A tile 128x32 (row=t>>1, 16 cols), B tile 32x128 (row=t>>3, 16 cols)
    const int ar = t >> 1, ac = (t & 1) * 16;
    const int br = t >> 3, bc = (t & 7) * 16;

    const float* Ap = (MODE == 2) ? (const float*)g_ctx : A;
    const float* Aptr = Ap + (size_t)(m0 + ar) * K + ac;
    const float* Bptr = Bm + (size_t)br * N + n0 + bc;

    float acc[2][8][4] = {};

    float4 aw[4], bw[4];
    #pragma unroll
    for (int i = 0; i < 4; i++) {
        aw[i] = *(const float4*)(Aptr + i * 4);
        bw[i] = *(const float4*)(Bptr + i * 4);
    }

    // ldmatrix lane address components (constant per thread)
    const int lrow = (lane & 7) + ((lane >> 3) & 1) * 8;  // row-in-group
    const int lcol8 = (lane >> 4) * 8;                    // col offset

    for (int k0 = 0; k0 < K; k0 += 32) {
        // convert + store to smem
        #pragma unroll
        for (int i = 0; i < 4; i++) {
            uint32_t h0, l0, h1, l1;
            split2(aw[i].x, aw[i].y, h0, l0);
            split2(aw[i].z, aw[i].w, h1, l1);
            uint32_t* ph = (uint32_t*)(Ahi + ar * ASTR + ac + 4 * i);
            uint32_t* pl = (uint32_t*)(Alo + ar * ASTR + ac + 4 * i);
            ph[0] = h0; ph[1] = h1; pl[0] = l0; pl[1] = l1;
            split2(bw[i].x, bw[i].y, h0, l0);
            split2(bw[i].z, bw[i].w, h1, l1);
            uint32_t* qh = (uint32_t*)(Bhi + br * BSTR + bc + 4 * i);
            uint32_t* ql = (uint32_t*)(Blo + br * BSTR + bc + 4 * i);
            qh[0] = h0; qh[1] = h1; ql[0] = l0; ql[1] = l1;
        }
        __syncthreads();

        if (k0 + 32 < K) {
            #pragma unroll
            for (int i = 0; i < 4; i++) {
                aw[i] = *(const float4*)(Aptr + k0 + 32 + i * 4);
                bw[i] = *(const float4*)(Bptr + (size_t)(k0 + 32) * N + i * 4);
            }
        }

        #pragma unroll
        for (int p = 0; p < 3; p++) {
            const __nv_bfloat16* Ap_s = (p < 2) ? Ahi : Alo;
            const __nv_bfloat16* Bp_s = (p == 1) ? Blo : Bhi;
            #pragma unroll
            for (int ks = 0; ks < 2; ks++) {
                uint32_t a[2][4];
                #pragma unroll
                for (int mf = 0; mf < 2; mf++) {
                    uint32_t ad = sptr(Ap_s + (wm + mf * 16 + lrow) * ASTR +
                                       ks * 16 + lcol8);
                    LDSM4(a[mf][0], a[mf][1], a[mf][2], a[mf][3], ad);
                }
                uint32_t bfr[8][2];
                #pragma unroll
                for (int nf2 = 0; nf2 < 4; nf2++) {
                    uint32_t r0, r1, r2, r3;
                    uint32_t bd = sptr(Bp_s + (ks * 16 + lrow) * BSTR +
                                       wn + nf2 * 16 + lcol8);
                    LDSM4T(r0, r1, r2, r3, bd);
                    bfr[2 * nf2][0] = r0;     bfr[2 * nf2][1] = r1;
                    bfr[2 * nf2 + 1][0] = r2; bfr[2 * nf2 + 1][1] = r3;
                }
                #pragma unroll
                for (int mf = 0; mf < 2; mf++)
                    #pragma unroll
                    for (int nf = 0; nf < 8; nf++)
                        mma16816(acc[mf][nf], a[mf], bfr[nf][0], bfr[nf][1]);
            }
        }
        __syncthreads();
    }

    // epilogue
    const int g = lane >> 2, tg = lane & 3;
    #pragma unroll
    for (int mf = 0; mf < 2; mf++) {
        #pragma unroll
        for (int nf = 0; nf < 8; nf++) {
            const int col = n0 + wn + nf * 8 + 2 * tg;
            #pragma unroll
            for (int half = 0; half < 2; half++) {
                const int row = m0 + wm + mf * 16 + g + half * 8;
                float2 v = make_float2(acc[mf][nf][half * 2],
                                       acc[mf][nf][half * 2 + 1]);
                if (MODE == 1) {
                    const int which = col / Hh;
                    const int rem = col - which * Hh;
                    const int head = rem >> 6, d0 = rem & 63;
                    const int bb = row >> 11, ss = row & (Ss - 1);
                    const size_t off =
                        ((((size_t)which * Bb + bb) * NH + head) * Ss + ss) * HD + d0;
                    *(float2*)(g_qkv + off) = v;
                } else {
                    *(float2*)(C + (size_t)row * N + col) = v;
                }
            }
        }
    }
}

// ---------------------------------------------------------------------------
// Flash attention, bf16x3 mma. CTA: 128 q-rows, 4 warps (32 q-rows each).
// KV tile 64. Smem layouts [row][col] stride 72 halves.
// ---------------------------------------------------------------------------
#define QSTR 72

__global__ void __launch_bounds__(128)
attn_mma()
{
    extern __shared__ __align__(16) __nv_bfloat16 sm[];
    __nv_bfloat16* Qhi = sm;                    // 128*72
    __nv_bfloat16* Qlo = Qhi + 128 * QSTR;
    __nv_bfloat16* Khi = Qlo + 128 * QSTR;      // 64*72
    __nv_bfloat16* Klo = Khi + 64 * QSTR;
    __nv_bfloat16* Vhi = Klo + 64 * QSTR;
    __nv_bfloat16* Vlo = Vhi + 64 * QSTR;

    const int t = threadIdx.x;
    const int lane = t & 31, warp = t >> 5;
    const int iq = blockIdx.x, h = blockIdx.y, b = blockIdx.z;
    const int wm = warp * 32;
    const int g = lane >> 2, tg = lane & 3;
    const int lrow = (lane & 7) + ((lane >> 3) & 1) * 8;
    const int lcol8 = (lane >> 4) * 8;

    const size_t head_off = (((size_t)b * NH) + h) * (size_t)Ss * HD;
    const size_t plane = (size_t)Bb * NH * Ss * HD;
    const float* Qg = g_qkv + head_off + (size_t)iq * 128 * HD;
    const float* Kg = g_qkv + plane + head_off;
    const float* Vg = g_qkv + 2 * plane + head_off;

    // Load Q (128x64): one row per thread
    #pragma unroll
    for (int i = 0; i < 16; i++) {
        float4 v = *(const float4*)(Qg + t * HD + i * 4);
        uint32_t h0, l0, h1, l1;
        split2(v.x, v.y, h0, l0);
        split2(v.z, v.w, h1, l1);
        uint32_t* ph = (uint32_t*)(Qhi + t * QSTR + i * 4);
        uint32_t* pl = (uint32_t*)(Qlo + t * QSTR + i * 4);
        ph[0] = h0; ph[1] = h1; pl[0] = l0; pl[1] = l1;
    }

    float o[2][8][4] = {};
    float mi[4], li[4];
    #pragma unroll
    for (int i = 0; i < 4; i++) { mi[i] = -1e30f; li[i] = 0.f; }

    const int njt = 2 * iq + 2;
    for (int jt = 0; jt < njt; jt++) {
        __syncthreads();   // prior S/O reads of K/V smem complete (and Q store)
        // Load K,V tile (64x64 each): row = t>>1, 32 cols
        {
            const int r = t >> 1, c0 = (t & 1) * 32;
            #pragma unroll
            for (int i = 0; i < 8; i++) {
                float4 kv = *(const float4*)(Kg + (size_t)(jt * 64 + r) * HD + c0 + i * 4);
                uint32_t h0, l0, h1, l1;
                split2(kv.x, kv.y, h0, l0);
                split2(kv.z, kv.w, h1, l1);
                uint32_t* ph = (uint32_t*)(Khi + r * QSTR + c0 + i * 4);
                uint32_t* pl = (uint32_t*)(Klo + r * QSTR + c0 + i * 4);
                ph[0] = h0; ph[1] = h1; pl[0] = l0; pl[1] = l1;
                float4 vv = *(const float4*)(Vg + (size_t)(jt * 64 + r) * HD + c0 + i * 4);
                split2(vv.x, vv.y, h0, l0);
                split2(vv.z, vv.w, h1, l1);
                ph = (uint32_t*)(Vhi + r * QSTR + c0 + i * 4);
                pl = (uint32_t*)(Vlo + r * QSTR + c0 + i * 4);
                ph[0] = h0; ph[1] = h1; pl[0] = l0; pl[1] = l1;
            }
        }
        __syncthreads();

        // ---- S = Q @ K^T (32x64x64 per warp), 3 passes ----
        float s[2][8][4] = {};
        #pragma unroll
        for (int p = 0; p < 3; p++) {
            const __nv_bfloat16* Qp = (p < 2) ? Qhi : Qlo;
            const __nv_bfloat16* Kp = (p == 1) ? Klo : Khi;
            #pragma unroll
            for (int ks = 0; ks < 4; ks++) {   // d chunks of 16
                uint32_t a[2][4];
                #pragma unroll
                for (int mf = 0; mf < 2; mf++) {
                    uint32_t ad = sptr(Qp + (wm + mf * 16 + lrow) * QSTR +
                                       ks * 16 + lcol8);
                    LDSM4(a[mf][0], a[mf][1], a[mf][2], a[mf][3], ad);
                }
                uint32_t bfr[8][2];
                #pragma unroll
                for (int kf2 = 0; kf2 < 4; kf2++) {  // key chunks of 16
                    uint32_t r0, r1, r2, r3;
                    // non-trans: row = key, col = d
                    uint32_t bd = sptr(Kp + (kf2 * 16 + (lane >> 4) * 8 + (lane & 7)) * QSTR +
                                       ks * 16 + ((lane >> 3) & 1) * 8);
                    LDSM4(r0, r1, r2, r3, bd);
                    bfr[2 * kf2][0] = r0;     bfr[2 * kf2][1] = r1;
                    bfr[2 * kf2 + 1][0] = r2; bfr[2 * kf2 + 1][1] = r3;
                }
                #pragma unroll
                for (int mf = 0; mf < 2; mf++)
                    #pragma unroll
                    for (int nf = 0; nf < 8; nf++)
                        mma16816(s[mf][nf], a[mf], bfr[nf][0], bfr[nf][1]);
            }
        }

        // ---- scale, mask, online softmax ----
        #pragma unroll
        for (int mf = 0; mf < 2; mf++)
            #pragma unroll
            for (int nf = 0; nf < 8; nf++)
                #pragma unroll
                for (int c = 0; c < 4; c++)
                    s[mf][nf][c] *= 0.125f;

        if (jt >= 2 * iq) {
            #pragma unroll
            for (int mf = 0; mf < 2; mf++)
                #pragma unroll
                for (int nf = 0; nf < 8; nf++)
                    #pragma unroll
                    for (int c = 0; c < 4; c++) {
                        int q = iq * 128 + wm + mf * 16 + g + (c >> 1) * 8;
                        int col = jt * 64 + nf * 8 + 2 * tg + (c & 1);
                        if (col > q) s[mf][nf][c] = -1e30f;
                    }
        }

        float fs[4];
        #pragma unroll
        for (int mf = 0; mf < 2; mf++) {
            #pragma unroll
            for (int half = 0; half < 2; half++) {
                const int ri = mf * 2 + half;
                float mt = -1e30f;
                #pragma unroll
                for (int nf = 0; nf < 8; nf++) {
                    mt = fmaxf(mt, s[mf][nf][half * 2]);
                    mt = fmaxf(mt, s[mf][nf][half * 2 + 1]);
                }
                mt = fmaxf(mt, __shfl_xor_sync(0xffffffffu, mt, 1));
                mt = fmaxf(mt, __shfl_xor_sync(0xffffffffu, mt, 2));
                float mn = fmaxf(mi[ri], mt);
                float f = __expf(mi[ri] - mn);
                float rs = 0.f;
                #pragma unroll
                for (int nf = 0; nf < 8; nf++) {
                    float e0 = __expf(s[mf][nf][half * 2] - mn);
                    float e1 = __expf(s[mf][nf][half * 2 + 1] - mn);
                    s[mf][nf][half * 2] = e0;
                    s[mf][nf][half * 2 + 1] = e1;
                    rs += e0 + e1;
                }
                rs += __shfl_xor_sync(0xffffffffu, rs, 1);
                rs += __shfl_xor_sync(0xffffffffu, rs, 2);
                li[ri] = li[ri] * f + rs;
                mi[ri] = mn;
                fs[ri] = f;
            }
        }
        #pragma unroll
        for (int mf = 0; mf < 2; mf++)
            #pragma unroll
            for (int nf = 0; nf < 8; nf++)
                #pragma unroll
                for (int c = 0; c < 4; c++)
                    o[mf][nf][c] *= fs[mf * 2 + (c >> 1)];

        // ---- O += P @ V (32x64 x kv64 per warp), 3 passes ----
        #pragma unroll
        for (int p = 0; p < 3; p++) {
            const __nv_bfloat16* Vp = (p == 1) ? Vlo : Vhi;
            const bool loP = (p == 2);
            #pragma unroll
            for (int ks = 0; ks < 4; ks++) {   // key chunks of 16
                uint32_t a[2][4];
                #pragma unroll
                for (int mf = 0; mf < 2; mf++) {
                    const float* c0 = s[mf][2 * ks];
                    const float* c1 = s[mf][2 * ks + 1];
                    if (!loP) {
                        a[mf][0] = packbf(c0[0], c0[1]);
                        a[mf][1] = packbf(c0[2], c0[3]);
                        a[mf][2] = packbf(c1[0], c1[1]);
                        a[mf][3] = packbf(c1[2], c1[3]);
                    } else {
                        uint32_t hi;
                        float2 hf;
                        hi = packbf(c0[0], c0[1]); hf = unpackbf(hi);
                        a[mf][0] = packbf(c0[0] - hf.x, c0[1] - hf.y);
                        hi = packbf(c0[2], c0[3]); hf = unpackbf(hi);
                        a[mf][1] = packbf(c0[2] - hf.x, c0[3] - hf.y);
                        hi = packbf(c1[0], c1[1]); hf = unpackbf(hi);
                        a[mf][2] = packbf(c1[0] - hf.x, c1[1] - hf.y);
                        hi = packbf(c1[2], c1[3]); hf = unpackbf(hi);
                        a[mf][3] = packbf(c1[2] - hf.x, c1[3] - hf.y);
                    }
                }
                uint32_t bfr[8][2];
                #pragma unroll
                for (int df2 = 0; df2 < 4; df2++) {  // d chunks of 16
                    uint32_t r0, r1, r2, r3;
                    // trans: row = key, col = d
                    uint32_t bd = sptr(Vp + (ks * 16 + lrow) * QSTR +
                                       df2 * 16 + lcol8);
                    LDSM4T(r0, r1, r2, r3, bd);
                    bfr[2 * df2][0] = r0;     bfr[2 * df2][1] = r1;
                    bfr[2 * df2 + 1][0] = r2; bfr[2 * df2 + 1][1] = r3;
                }
                #pragma unroll
                for (int mf = 0; mf < 2; mf++)
                    #pragma unroll
                    for (int nf = 0; nf < 8; nf++)
                        mma16816(o[mf][nf], a[mf], bfr[nf][0], bfr[nf][1]);
            }
        }
    }

    // epilogue: normalize, write g_ctx [b][s][h*64+d]
    #pragma unroll
    for (int mf = 0; mf < 2; mf++) {
        #pragma unroll
        for (int half = 0; half < 2; half++) {
            const int ri = mf * 2 + half;
            const float inv = 1.0f / li[ri];
            const int row = iq * 128 + wm + mf * 16 + g + half * 8;
            #pragma unroll
            for (int nf = 0; nf < 8; nf++) {
                const int col = nf * 8 + 2 * tg;
                float2 v = make_float2(o[mf][nf][half * 2] * inv,
                                       o[mf][nf][half * 2 + 1] * inv);
                *(float2*)(g_ctx + ((size_t)b * Ss + row) * Hh + h * HD + col) = v;
            }
        }
    }
}

// ---------------------------------------------------------------------------

extern "C" void kernel_launch(void* const* d_in, const int* in_sizes, int n_in,
                              void* d_out, int out_size)
{
    const float* x    = (const float*)d_in[0];   // [4,2048,768]
    const float* wqkv = (const float*)d_in[1];   // [768,2304]
    const float* wout = (const float*)d_in[2];   // [768,768]
    float* out = (float*)d_out;                  // [4,2048,768]

    // 1) QKV projection (scatter into g_qkv)
    gemm_mma<1><<<dim3(2304 / 128, 8192 / 128), 256>>>(x, wqkv, nullptr,
                                                       Bb * Ss, 3 * Hh, Hh);

    // 2) Flash attention (causal), dynamic smem
    const int SMEM = (128 * QSTR * 2 + 64 * QSTR * 4) * (int)sizeof(__nv_bfloat16);
    cudaFuncSetAttribute(attn_mma,
                         cudaFuncAttributeMaxDynamicSharedMemorySize, SMEM);
    attn_mma<<<dim3(Ss / 128, NH, Bb), 128, SMEM>>>();

    // 3) Output projection
    gemm_mma<2><<<dim3(768 / 128, 8192 / 128), 256>>>(nullptr, wout, out,
                                                      Bb * Ss, Hh, Hh);
}

// round 5
// speedup vs baseline: 2.8979x; 1.3588x over previous
#include <cuda_runtime.h>
#include <cuda_bf16.h>
#include <stdint.h>
#include <math.h>

#define Bb 4
#define Ss 2048
#define Hh 768
#define NH 12
#define HD 64

// ---------------------------------------------------------------------------
// Scratch (allocation-free rule: __device__ globals) — bf16 hi/lo planes
// ---------------------------------------------------------------------------
__device__ __nv_bfloat16 g_xh[Bb * Ss * Hh],  g_xl[Bb * Ss * Hh];
__device__ __nv_bfloat16 g_wqh[Hh * 3 * Hh],  g_wql[Hh * 3 * Hh];
__device__ __nv_bfloat16 g_woh[Hh * Hh],      g_wol[Hh * Hh];
__device__ __nv_bfloat16 g_qkvh[3 * Bb * NH * Ss * HD], g_qkvl[3 * Bb * NH * Ss * HD];
__device__ __nv_bfloat16 g_ctxh[Bb * Ss * Hh], g_ctxl[Bb * Ss * Hh];

// ---------------------------------------------------------------------------
// Helpers
// ---------------------------------------------------------------------------
__device__ __forceinline__ uint32_t packbf(float lo, float hi) {
    uint32_t r;
    asm("cvt.rn.bf16x2.f32 %0, %1, %2;" : "=r"(r) : "f"(hi), "f"(lo));
    return r;
}
__device__ __forceinline__ float2 unpackbf(uint32_t u) {
    __nv_bfloat162 h = *reinterpret_cast<__nv_bfloat162*>(&u);
    return make_float2(__bfloat162float(h.x), __bfloat162float(h.y));
}
__device__ __forceinline__ void split2(float x, float y, uint32_t& hi, uint32_t& lo) {
    hi = packbf(x, y);
    float2 h = unpackbf(hi);
    lo = packbf(x - h.x, y - h.y);
}

#define LDSM4(r0, r1, r2, r3, a)                                              \
    asm volatile("ldmatrix.sync.aligned.m8n8.x4.shared.b16 {%0,%1,%2,%3}, [%4];" \
                 : "=r"(r0), "=r"(r1), "=r"(r2), "=r"(r3) : "r"(a))
#define LDSM4T(r0, r1, r2, r3, a)                                             \
    asm volatile("ldmatrix.sync.aligned.m8n8.x4.trans.shared.b16 {%0,%1,%2,%3}, [%4];" \
                 : "=r"(r0), "=r"(r1), "=r"(r2), "=r"(r3) : "r"(a))
#define CPA(dst, src)                                                         \
    asm volatile("cp.async.cg.shared.global [%0], [%1], 16;" :: "r"(dst), "l"(src))
#define CPCOMMIT() asm volatile("cp.async.commit_group;")
#define CPWAIT0()  asm volatile("cp.async.wait_group 0;")
#define CPWAIT1()  asm volatile("cp.async.wait_group 1;")

__device__ __forceinline__ void mma16816(float* c, const uint32_t* a,
                                         uint32_t b0, uint32_t b1) {
    asm volatile(
        "mma.sync.aligned.m16n8k16.row.col.f32.bf16.bf16.f32 "
        "{%0,%1,%2,%3}, {%4,%5,%6,%7}, {%8,%9}, {%0,%1,%2,%3};"
        : "+f"(c[0]), "+f"(c[1]), "+f"(c[2]), "+f"(c[3])
        : "r"(a[0]), "r"(a[1]), "r"(a[2]), "r"(a[3]), "r"(b0), "r"(b1));
}
__device__ __forceinline__ uint32_t sptr(const void* p) {
    return (uint32_t)__cvta_generic_to_shared(p);
}

// ---------------------------------------------------------------------------
// fp32 -> bf16 hi/lo convert prepass
// ---------------------------------------------------------------------------
__global__ void cvt_kernel(const float* __restrict__ in,
                           __nv_bfloat16* __restrict__ hi,
                           __nv_bfloat16* __restrict__ lo, int n)
{
    int i = (blockIdx.x * blockDim.x + threadIdx.x) * 4;
    if (i < n) {
        float4 v = *(const float4*)(in + i);
        uint32_t h0, l0, h1, l1;
        split2(v.x, v.y, h0, l0);
        split2(v.z, v.w, h1, l1);
        uint32_t* ph = (uint32_t*)(hi + i);
        uint32_t* pl = (uint32_t*)(lo + i);
        ph[0] = h0; ph[1] = h1;
        pl[0] = l0; pl[1] = l1;
    }
}

// ---------------------------------------------------------------------------
// Projection GEMM on preconverted bf16: 128x128 tile, BK=32, 8 warps,
// cp.async double-buffered, 3 passes (hh + hl + lh).
// MODE 1: scatter epilogue -> g_qkvh/l. MODE 2: fp32 C.
// ---------------------------------------------------------------------------
#define ASTR 40
#define BSTR 136
#define GEMM_SMEM ((2 * 128 * ASTR * 2 + 2 * 32 * BSTR * 2) * 2)  // bytes

template <int MODE>
__global__ void __launch_bounds__(256, 2)
gemm_bf(const __nv_bfloat16* __restrict__ Ah, const __nv_bfloat16* __restrict__ Al,
        const __nv_bfloat16* __restrict__ Bh, const __nv_bfloat16* __restrict__ Bl,
        float* __restrict__ C, int M, int N, int K)
{
    extern __shared__ __align__(16) __nv_bfloat16 smg[];
    __nv_bfloat16* Ahs = smg;                        // [2][128*ASTR]
    __nv_bfloat16* Als = Ahs + 2 * 128 * ASTR;
    __nv_bfloat16* Bhs = Als + 2 * 128 * ASTR;       // [2][32*BSTR]
    __nv_bfloat16* Bls = Bhs + 2 * 32 * BSTR;

    const int t = threadIdx.x;
    const int lane = t & 31, warp = t >> 5;
    const int m0 = blockIdx.y * 128, n0 = blockIdx.x * 128;
    const int wm = (warp >> 1) * 32, wn = (warp & 1) * 64;
    const int lrow = (lane & 7) + ((lane >> 3) & 1) * 8;
    const int lcol8 = (lane >> 4) * 8;

    auto issue = [&](int st, int k0) {
        #pragma unroll
        for (int i = 0; i < 2; i++) {
            int c = t + i * 256;
            int row = c >> 2, co = (c & 3) * 8;
            uint32_t da = st * 128 * ASTR + row * ASTR + co;
            size_t sa = (size_t)(m0 + row) * K + k0 + co;
            CPA(sptr(Ahs + da), Ah + sa);
            CPA(sptr(Als + da), Al + sa);
            int rb = c >> 4, cb = (c & 15) * 8;
            uint32_t db = st * 32 * BSTR + rb * BSTR + cb;
            size_t sb = (size_t)(k0 + rb) * N + n0 + cb;
            CPA(sptr(Bhs + db), Bh + sb);
            CPA(sptr(Bls + db), Bl + sb);
        }
    };

    float acc[2][8][4] = {};
    int st = 0;
    issue(0, 0);
    CPCOMMIT();

    for (int k0 = 0; k0 < K; k0 += 32) {
        if (k0 + 32 < K) { issue(st ^ 1, k0 + 32); CPCOMMIT(); CPWAIT1(); }
        else             { CPWAIT0(); }
        __syncthreads();

        const __nv_bfloat16* Ahb = Ahs + st * 128 * ASTR;
        const __nv_bfloat16* Alb = Als + st * 128 * ASTR;
        const __nv_bfloat16* Bhb = Bhs + st * 32 * BSTR;
        const __nv_bfloat16* Blb = Bls + st * 32 * BSTR;

        #pragma unroll
        for (int p = 0; p < 3; p++) {
            const __nv_bfloat16* Ap_s = (p < 2) ? Ahb : Alb;
            const __nv_bfloat16* Bp_s = (p == 1) ? Blb : Bhb;
            #pragma unroll
            for (int ks = 0; ks < 2; ks++) {
                uint32_t a[2][4];
                #pragma unroll
                for (int mf = 0; mf < 2; mf++) {
                    uint32_t ad = sptr(Ap_s + (wm + mf * 16 + lrow) * ASTR +
                                       ks * 16 + lcol8);
                    LDSM4(a[mf][0], a[mf][1], a[mf][2], a[mf][3], ad);
                }
                uint32_t bfr[8][2];
                #pragma unroll
                for (int nf2 = 0; nf2 < 4; nf2++) {
                    uint32_t r0, r1, r2, r3;
                    uint32_t bd = sptr(Bp_s + (ks * 16 + lrow) * BSTR +
                                       wn + nf2 * 16 + lcol8);
                    LDSM4T(r0, r1, r2, r3, bd);
                    bfr[2 * nf2][0] = r0;     bfr[2 * nf2][1] = r1;
                    bfr[2 * nf2 + 1][0] = r2; bfr[2 * nf2 + 1][1] = r3;
                }
                #pragma unroll
                for (int mf = 0; mf < 2; mf++)
                    #pragma unroll
                    for (int nf = 0; nf < 8; nf++)
                        mma16816(acc[mf][nf], a[mf], bfr[nf][0], bfr[nf][1]);
            }
        }
        __syncthreads();
        st ^= 1;
    }

    // epilogue
    const int g = lane >> 2, tg = lane & 3;
    #pragma unroll
    for (int mf = 0; mf < 2; mf++) {
        #pragma unroll
        for (int nf = 0; nf < 8; nf++) {
            const int col = n0 + wn + nf * 8 + 2 * tg;
            #pragma unroll
            for (int half = 0; half < 2; half++) {
                const int row = m0 + wm + mf * 16 + g + half * 8;
                float vx = acc[mf][nf][half * 2], vy = acc[mf][nf][half * 2 + 1];
                if (MODE == 1) {
                    const int which = col / Hh;
                    const int rem = col - which * Hh;
                    const int head = rem >> 6, d0 = rem & 63;
                    const int bb = row >> 11, ss = row & (Ss - 1);
                    const size_t off =
                        ((((size_t)which * Bb + bb) * NH + head) * Ss + ss) * HD + d0;
                    uint32_t hi, lo;
                    split2(vx, vy, hi, lo);
                    *(uint32_t*)(g_qkvh + off) = hi;
                    *(uint32_t*)(g_qkvl + off) = lo;
                } else {
                    *(float2*)(C + (size_t)row * N + col) = make_float2(vx, vy);
                }
            }
        }
    }
}

// ---------------------------------------------------------------------------
// Flash attention on preconverted bf16 hi/lo Q/K/V. 128 q-rows, 4 warps.
// KV tile 64, cp.async double-buffered. Epilogue writes ctx hi/lo bf16.
// ---------------------------------------------------------------------------
#define QSTR 72
#define ATTN_SMEM ((2 * 128 * QSTR + 8 * 64 * QSTR) * 2)  // bytes

__global__ void __launch_bounds__(128)
attn_bf()
{
    extern __shared__ __align__(16) __nv_bfloat16 sma[];
    __nv_bfloat16* Qhi = sma;                        // 128*QSTR
    __nv_bfloat16* Qlo = Qhi + 128 * QSTR;
    __nv_bfloat16* Khs = Qlo + 128 * QSTR;           // [2][64*QSTR]
    __nv_bfloat16* Kls = Khs + 2 * 64 * QSTR;
    __nv_bfloat16* Vhs = Kls + 2 * 64 * QSTR;
    __nv_bfloat16* Vls = Vhs + 2 * 64 * QSTR;

    const int t = threadIdx.x;
    const int lane = t & 31, warp = t >> 5;
    const int iq = blockIdx.x, h = blockIdx.y, b = blockIdx.z;
    const int wm = warp * 32;
    const int g = lane >> 2, tg = lane & 3;
    const int lrow = (lane & 7) + ((lane >> 3) & 1) * 8;
    const int lcol8 = (lane >> 4) * 8;

    const size_t head_off = (((size_t)b * NH) + h) * (size_t)Ss * HD;
    const size_t plane = (size_t)Bb * NH * Ss * HD;
    const __nv_bfloat16* Qgh = g_qkvh + head_off + (size_t)iq * 128 * HD;
    const __nv_bfloat16* Qgl = g_qkvl + head_off + (size_t)iq * 128 * HD;
    const __nv_bfloat16* Kgh = g_qkvh + plane + head_off;
    const __nv_bfloat16* Kgl = g_qkvl + plane + head_off;
    const __nv_bfloat16* Vgh = g_qkvh + 2 * plane + head_off;
    const __nv_bfloat16* Vgl = g_qkvl + 2 * plane + head_off;

    auto issue_kv = [&](int jt, int stg) {
        #pragma unroll
        for (int i = 0; i < 4; i++) {
            int c = t + i * 128;                  // 0..511
            int row = c >> 3, co = (c & 7) * 8;
            size_t src = (size_t)(jt * 64 + row) * HD + co;
            uint32_t doff = stg * 64 * QSTR + row * QSTR + co;
            CPA(sptr(Khs + doff), Kgh + src);
            CPA(sptr(Kls + doff), Kgl + src);
            CPA(sptr(Vhs + doff), Vgh + src);
            CPA(sptr(Vls + doff), Vgl + src);
        }
    };

    int st = 0;
    issue_kv(0, 0);
    CPCOMMIT();

    // Load Q (128x64 bf16 hi/lo): one row per thread
    #pragma unroll
    for (int i = 0; i < 8; i++) {
        *(uint4*)(Qhi + t * QSTR + i * 8) = *(const uint4*)(Qgh + t * HD + i * 8);
        *(uint4*)(Qlo + t * QSTR + i * 8) = *(const uint4*)(Qgl + t * HD + i * 8);
    }

    float o[2][8][4] = {};
    float mi[4], li[4];
    #pragma unroll
    for (int i = 0; i < 4; i++) { mi[i] = -1e30f; li[i] = 0.f; }

    const int njt = 2 * iq + 2;
    for (int jt = 0; jt < njt; jt++) {
        if (jt + 1 < njt) { issue_kv(jt + 1, st ^ 1); CPCOMMIT(); CPWAIT1(); }
        else              { CPWAIT0(); }
        __syncthreads();

        const __nv_bfloat16* Khb = Khs + st * 64 * QSTR;
        const __nv_bfloat16* Klb = Kls + st * 64 * QSTR;
        const __nv_bfloat16* Vhb = Vhs + st * 64 * QSTR;
        const __nv_bfloat16* Vlb = Vls + st * 64 * QSTR;

        // ---- S = Q @ K^T (32x64x64 per warp), 3 passes ----
        float s[2][8][4] = {};
        #pragma unroll
        for (int p = 0; p < 3; p++) {
            const __nv_bfloat16* Qp = (p < 2) ? Qhi : Qlo;
            const __nv_bfloat16* Kp = (p == 1) ? Klb : Khb;
            #pragma unroll
            for (int ks = 0; ks < 4; ks++) {
                uint32_t a[2][4];
                #pragma unroll
                for (int mf = 0; mf < 2; mf++) {
                    uint32_t ad = sptr(Qp + (wm + mf * 16 + lrow) * QSTR +
                                       ks * 16 + lcol8);
                    LDSM4(a[mf][0], a[mf][1], a[mf][2], a[mf][3], ad);
                }
                uint32_t bfr[8][2];
                #pragma unroll
                for (int kf2 = 0; kf2 < 4; kf2++) {
                    uint32_t r0, r1, r2, r3;
                    uint32_t bd = sptr(Kp + (kf2 * 16 + (lane >> 4) * 8 + (lane & 7)) * QSTR +
                                       ks * 16 + ((lane >> 3) & 1) * 8);
                    LDSM4(r0, r1, r2, r3, bd);
                    bfr[2 * kf2][0] = r0;     bfr[2 * kf2][1] = r1;
                    bfr[2 * kf2 + 1][0] = r2; bfr[2 * kf2 + 1][1] = r3;
                }
                #pragma unroll
                for (int mf = 0; mf < 2; mf++)
                    #pragma unroll
                    for (int nf = 0; nf < 8; nf++)
                        mma16816(s[mf][nf], a[mf], bfr[nf][0], bfr[nf][1]);
            }
        }

        // ---- scale, mask, online softmax ----
        #pragma unroll
        for (int mf = 0; mf < 2; mf++)
            #pragma unroll
            for (int nf = 0; nf < 8; nf++)
                #pragma unroll
                for (int c = 0; c < 4; c++)
                    s[mf][nf][c] *= 0.125f;

        if (jt >= 2 * iq) {
            #pragma unroll
            for (int mf = 0; mf < 2; mf++)
                #pragma unroll
                for (int nf = 0; nf < 8; nf++)
                    #pragma unroll
                    for (int c = 0; c < 4; c++) {
                        int q = iq * 128 + wm + mf * 16 + g + (c >> 1) * 8;
                        int col = jt * 64 + nf * 8 + 2 * tg + (c & 1);
                        if (col > q) s[mf][nf][c] = -1e30f;
                    }
        }

        float fs[4];
        #pragma unroll
        for (int mf = 0; mf < 2; mf++) {
            #pragma unroll
            for (int half = 0; half < 2; half++) {
                const int ri = mf * 2 + half;
                float mt = -1e30f;
                #pragma unroll
                for (int nf = 0; nf < 8; nf++) {
                    mt = fmaxf(mt, s[mf][nf][half * 2]);
                    mt = fmaxf(mt, s[mf][nf][half * 2 + 1]);
                }
                mt = fmaxf(mt, __shfl_xor_sync(0xffffffffu, mt, 1));
                mt = fmaxf(mt, __shfl_xor_sync(0xffffffffu, mt, 2));
                float mn = fmaxf(mi[ri], mt);
                float f = __expf(mi[ri] - mn);
                float rs = 0.f;
                #pragma unroll
                for (int nf = 0; nf < 8; nf++) {
                    float e0 = __expf(s[mf][nf][half * 2] - mn);
                    float e1 = __expf(s[mf][nf][half * 2 + 1] - mn);
                    s[mf][nf][half * 2] = e0;
                    s[mf][nf][half * 2 + 1] = e1;
                    rs += e0 + e1;
                }
                rs += __shfl_xor_sync(0xffffffffu, rs, 1);
                rs += __shfl_xor_sync(0xffffffffu, rs, 2);
                li[ri] = li[ri] * f + rs;
                mi[ri] = mn;
                fs[ri] = f;
            }
        }
        #pragma unroll
        for (int mf = 0; mf < 2; mf++)
            #pragma unroll
            for (int nf = 0; nf < 8; nf++)
                #pragma unroll
                for (int c = 0; c < 4; c++)
                    o[mf][nf][c] *= fs[mf * 2 + (c >> 1)];

        // ---- O += P @ V, 3 passes ----
        #pragma unroll
        for (int p = 0; p < 3; p++) {
            const __nv_bfloat16* Vp = (p == 1) ? Vlb : Vhb;
            const bool loP = (p == 2);
            #pragma unroll
            for (int ks = 0; ks < 4; ks++) {
                uint32_t a[2][4];
                #pragma unroll
                for (int mf = 0; mf < 2; mf++) {
                    const float* c0 = s[mf][2 * ks];
                    const float* c1 = s[mf][2 * ks + 1];
                    if (!loP) {
                        a[mf][0] = packbf(c0[0], c0[1]);
                        a[mf][1] = packbf(c0[2], c0[3]);
                        a[mf][2] = packbf(c1[0], c1[1]);
                        a[mf][3] = packbf(c1[2], c1[3]);
                    } else {
                        uint32_t hi;
                        float2 hf;
                        hi = packbf(c0[0], c0[1]); hf = unpackbf(hi);
                        a[mf][0] = packbf(c0[0] - hf.x, c0[1] - hf.y);
                        hi = packbf(c0[2], c0[3]); hf = unpackbf(hi);
                        a[mf][1] = packbf(c0[2] - hf.x, c0[3] - hf.y);
                        hi = packbf(c1[0], c1[1]); hf = unpackbf(hi);
                        a[mf][2] = packbf(c1[0] - hf.x, c1[1] - hf.y);
                        hi = packbf(c1[2], c1[3]); hf = unpackbf(hi);
                        a[mf][3] = packbf(c1[2] - hf.x, c1[3] - hf.y);
                    }
                }
                uint32_t bfr[8][2];
                #pragma unroll
                for (int df2 = 0; df2 < 4; df2++) {
                    uint32_t r0, r1, r2, r3;
                    uint32_t bd = sptr(Vp + (ks * 16 + lrow) * QSTR +
                                       df2 * 16 + lcol8);
                    LDSM4T(r0, r1, r2, r3, bd);
                    bfr[2 * df2][0] = r0;     bfr[2 * df2][1] = r1;
                    bfr[2 * df2 + 1][0] = r2; bfr[2 * df2 + 1][1] = r3;
                }
                #pragma unroll
                for (int mf = 0; mf < 2; mf++)
                    #pragma unroll
                    for (int nf = 0; nf < 8; nf++)
                        mma16816(o[mf][nf], a[mf], bfr[nf][0], bfr[nf][1]);
            }
        }
        __syncthreads();
        st ^= 1;
    }

    // epilogue: normalize, write ctx hi/lo bf16 [b][s][h*64+d]
    #pragma unroll
    for (int mf = 0; mf < 2; mf++) {
        #pragma unroll
        for (int half = 0; half < 2; half++) {
            const int ri = mf * 2 + half;
            const float inv = 1.0f / li[ri];
            const int row = iq * 128 + wm + mf * 16 + g + half * 8;
            #pragma unroll
            for (int nf = 0; nf < 8; nf++) {
                const int col = nf * 8 + 2 * tg;
                const size_t off = ((size_t)b * Ss + row) * Hh + h * HD + col;
                uint32_t hi, lo;
                split2(o[mf][nf][half * 2] * inv, o[mf][nf][half * 2 + 1] * inv,
                       hi, lo);
                *(uint32_t*)(g_ctxh + off) = hi;
                *(uint32_t*)(g_ctxl + off) = lo;
            }
        }
    }
}

// ---------------------------------------------------------------------------

extern "C" void kernel_launch(void* const* d_in, const int* in_sizes, int n_in,
                              void* d_out, int out_size)
{
    const float* x    = (const float*)d_in[0];   // [4,2048,768]
    const float* wqkv = (const float*)d_in[1];   // [768,2304]
    const float* wout = (const float*)d_in[2];   // [768,768]
    float* out = (float*)d_out;                  // [4,2048,768]

    __nv_bfloat16 *xh, *xl, *wqh, *wql, *woh, *wol;
    cudaGetSymbolAddress((void**)&xh,  g_xh);
    cudaGetSymbolAddress((void**)&xl,  g_xl);
    cudaGetSymbolAddress((void**)&wqh, g_wqh);
    cudaGetSymbolAddress((void**)&wql, g_wql);
    cudaGetSymbolAddress((void**)&woh, g_woh);
    cudaGetSymbolAddress((void**)&wol, g_wol);

    // 0) convert inputs to bf16 hi/lo
    cvt_kernel<<<(Bb * Ss * Hh / 4 + 255) / 256, 256>>>(x, xh, xl, Bb * Ss * Hh);
    cvt_kernel<<<(Hh * 3 * Hh / 4 + 255) / 256, 256>>>(wqkv, wqh, wql, Hh * 3 * Hh);
    cvt_kernel<<<(Hh * Hh / 4 + 255) / 256, 256>>>(wout, woh, wol, Hh * Hh);

    // 1) QKV projection (scatter into g_qkvh/l)
    cudaFuncSetAttribute(gemm_bf<1>,
                         cudaFuncAttributeMaxDynamicSharedMemorySize, GEMM_SMEM);
    gemm_bf<1><<<dim3(2304 / 128, 8192 / 128), 256, GEMM_SMEM>>>(
        xh, xl, wqh, wql, nullptr, Bb * Ss, 3 * Hh, Hh);

    // 2) Flash attention (causal)
    cudaFuncSetAttribute(attn_bf,
                         cudaFuncAttributeMaxDynamicSharedMemorySize, ATTN_SMEM);
    attn_bf<<<dim3(Ss / 128, NH, Bb), 128, ATTN_SMEM>>>();

    // 3) Output projection
    __nv_bfloat16 *ch, *cl;
    cudaGetSymbolAddress((void**)&ch, g_ctxh);
    cudaGetSymbolAddress((void**)&cl, g_ctxl);
    cudaFuncSetAttribute(gemm_bf<2>,
                         cudaFuncAttributeMaxDynamicSharedMemorySize, GEMM_SMEM);
    gemm_bf<2><<<dim3(768 / 128, 8192 / 128), 256, GEMM_SMEM>>>(
        ch, cl, woh, wol, out, Bb * Ss, Hh, Hh);
}

// round 7
// speedup vs baseline: 3.1424x; 1.0844x over previous
#include <cuda_runtime.h>
#include <cuda_bf16.h>
#include <stdint.h>
#include <math.h>

#define Bb 4
#define Ss 2048
#define Hh 768
#define NH 12
#define HD 64

// ---------------------------------------------------------------------------
// Scratch (allocation-free rule: __device__ globals) — bf16 hi/lo planes
// ---------------------------------------------------------------------------
__device__ __nv_bfloat16 g_xh[Bb * Ss * Hh],  g_xl[Bb * Ss * Hh];
__device__ __nv_bfloat16 g_wqh[Hh * 3 * Hh],  g_wql[Hh * 3 * Hh];
__device__ __nv_bfloat16 g_woh[Hh * Hh],      g_wol[Hh * Hh];
__device__ __nv_bfloat16 g_qkvh[3 * Bb * NH * Ss * HD], g_qkvl[3 * Bb * NH * Ss * HD];
__device__ __nv_bfloat16 g_ctxh[Bb * Ss * Hh], g_ctxl[Bb * Ss * Hh];

// ---------------------------------------------------------------------------
// Helpers
// ---------------------------------------------------------------------------
__device__ __forceinline__ uint32_t packbf(float lo, float hi) {
    uint32_t r;
    asm("cvt.rn.bf16x2.f32 %0, %1, %2;" : "=r"(r) : "f"(hi), "f"(lo));
    return r;
}
__device__ __forceinline__ float2 unpackbf(uint32_t u) {
    __nv_bfloat162 h = *reinterpret_cast<__nv_bfloat162*>(&u);
    return make_float2(__bfloat162float(h.x), __bfloat162float(h.y));
}
__device__ __forceinline__ void split2(float x, float y, uint32_t& hi, uint32_t& lo) {
    hi = packbf(x, y);
    float2 h = unpackbf(hi);
    lo = packbf(x - h.x, y - h.y);
}

#define LDSM4(r0, r1, r2, r3, a)                                              \
    asm volatile("ldmatrix.sync.aligned.m8n8.x4.shared.b16 {%0,%1,%2,%3}, [%4];" \
                 : "=r"(r0), "=r"(r1), "=r"(r2), "=r"(r3) : "r"(a))
#define LDSM4T(r0, r1, r2, r3, a)                                             \
    asm volatile("ldmatrix.sync.aligned.m8n8.x4.trans.shared.b16 {%0,%1,%2,%3}, [%4];" \
                 : "=r"(r0), "=r"(r1), "=r"(r2), "=r"(r3) : "r"(a))
#define CPA(dst, src)                                                         \
    asm volatile("cp.async.cg.shared.global [%0], [%1], 16;" :: "r"(dst), "l"(src))
#define CPCOMMIT() asm volatile("cp.async.commit_group;")
#define CPWAIT0()  asm volatile("cp.async.wait_group 0;")
#define CPWAIT1()  asm volatile("cp.async.wait_group 1;")

__device__ __forceinline__ void mma16816(float* c, const uint32_t* a,
                                         uint32_t b0, uint32_t b1) {
    asm volatile(
        "mma.sync.aligned.m16n8k16.row.col.f32.bf16.bf16.f32 "
        "{%0,%1,%2,%3}, {%4,%5,%6,%7}, {%8,%9}, {%0,%1,%2,%3};"
        : "+f"(c[0]), "+f"(c[1]), "+f"(c[2]), "+f"(c[3])
        : "r"(a[0]), "r"(a[1]), "r"(a[2]), "r"(a[3]), "r"(b0), "r"(b1));
}
__device__ __forceinline__ uint32_t sptr(const void* p) {
    return (uint32_t)__cvta_generic_to_shared(p);
}

// ---------------------------------------------------------------------------
// fp32 -> bf16 hi/lo convert prepass
// ---------------------------------------------------------------------------
__global__ void cvt_kernel(const float* __restrict__ in,
                           __nv_bfloat16* __restrict__ hi,
                           __nv_bfloat16* __restrict__ lo, int n)
{
    int i = (blockIdx.x * blockDim.x + threadIdx.x) * 4;
    if (i < n) {
        float4 v = *(const float4*)(in + i);
        uint32_t h0, l0, h1, l1;
        split2(v.x, v.y, h0, l0);
        split2(v.z, v.w, h1, l1);
        uint32_t* ph = (uint32_t*)(hi + i);
        uint32_t* pl = (uint32_t*)(lo + i);
        ph[0] = h0; ph[1] = h1;
        pl[0] = l0; pl[1] = l1;
    }
}

// ---------------------------------------------------------------------------
// Projection GEMM, bf16 hi/lo, 128x128 tile, BK=32, 8 warps (32x64 each),
// 3-stage cp.async, cross-pass operand reuse (hh + lh + hl).
// MODE 1: scatter epilogue -> g_qkvh/l. MODE 2: fp32 C.
// ---------------------------------------------------------------------------
#define ASTR 40
#define BSTR 136
#define STAGE_H (2 * 128 * ASTR + 2 * 32 * BSTR)          // halves per stage
#define GEMM_SMEM (3 * STAGE_H * 2)                       // bytes

template <int MODE>
__global__ void __launch_bounds__(256, 2)
gemm_bf(const __nv_bfloat16* __restrict__ Ah, const __nv_bfloat16* __restrict__ Al,
        const __nv_bfloat16* __restrict__ Bh, const __nv_bfloat16* __restrict__ Bl,
        float* __restrict__ C, int M, int N, int K)
{
    extern __shared__ __align__(16) __nv_bfloat16 smg[];

    const int t = threadIdx.x;
    const int lane = t & 31, warp = t >> 5;
    const int m0 = blockIdx.y * 128, n0 = blockIdx.x * 128;
    const int wm = (warp >> 1) * 32, wn = (warp & 1) * 64;
    const int lrow = (lane & 7) + ((lane >> 3) & 1) * 8;
    const int lcol8 = (lane >> 4) * 8;

    auto issue = [&](int stg, int k0) {
        __nv_bfloat16* Ahs = smg + stg * STAGE_H;
        __nv_bfloat16* Als = Ahs + 128 * ASTR;
        __nv_bfloat16* Bhs = Als + 128 * ASTR;
        __nv_bfloat16* Bls = Bhs + 32 * BSTR;
        #pragma unroll
        for (int i = 0; i < 2; i++) {
            int c = t + i * 256;
            int row = c >> 2, co = (c & 3) * 8;
            uint32_t da = row * ASTR + co;
            size_t sa = (size_t)(m0 + row) * K + k0 + co;
            CPA(sptr(Ahs + da), Ah + sa);
            CPA(sptr(Als + da), Al + sa);
            int rb = c >> 4, cb = (c & 15) * 8;
            uint32_t db = rb * BSTR + cb;
            size_t sb = (size_t)(k0 + rb) * N + n0 + cb;
            CPA(sptr(Bhs + db), Bh + sb);
            CPA(sptr(Bls + db), Bl + sb);
        }
    };

    float acc[2][8][4] = {};
    const int KT = K / 32;
    issue(0, 0);  CPCOMMIT();
    issue(1, 32); CPCOMMIT();

    for (int kt = 0; kt < KT; kt++) {
        const int st = kt % 3;
        if (kt + 1 < KT) CPWAIT1(); else CPWAIT0();
        __syncthreads();

        const __nv_bfloat16* Ahb = smg + st * STAGE_H;
        const __nv_bfloat16* Alb = Ahb + 128 * ASTR;
        const __nv_bfloat16* Bhb = Alb + 128 * ASTR;
        const __nv_bfloat16* Blb = Bhb + 32 * BSTR;

        #pragma unroll
        for (int ks = 0; ks < 2; ks++) {
            uint32_t ah[2][4], al[2][4];
            uint32_t bh[8][2], bl[8][2];
            #pragma unroll
            for (int mf = 0; mf < 2; mf++) {
                uint32_t ad = sptr(Ahb + (wm + mf * 16 + lrow) * ASTR + ks * 16 + lcol8);
                LDSM4(ah[mf][0], ah[mf][1], ah[mf][2], ah[mf][3], ad);
            }
            #pragma unroll
            for (int nf2 = 0; nf2 < 4; nf2++) {
                uint32_t r0, r1, r2, r3;
                uint32_t bd = sptr(Bhb + (ks * 16 + lrow) * BSTR + wn + nf2 * 16 + lcol8);
                LDSM4T(r0, r1, r2, r3, bd);
                bh[2 * nf2][0] = r0;     bh[2 * nf2][1] = r1;
                bh[2 * nf2 + 1][0] = r2; bh[2 * nf2 + 1][1] = r3;
            }
            #pragma unroll
            for (int mf = 0; mf < 2; mf++)          // hh
                #pragma unroll
                for (int nf = 0; nf < 8; nf++)
                    mma16816(acc[mf][nf], ah[mf], bh[nf][0], bh[nf][1]);
            #pragma unroll
            for (int mf = 0; mf < 2; mf++) {
                uint32_t ad = sptr(Alb + (wm + mf * 16 + lrow) * ASTR + ks * 16 + lcol8);
                LDSM4(al[mf][0], al[mf][1], al[mf][2], al[mf][3], ad);
            }
            #pragma unroll
            for (int mf = 0; mf < 2; mf++)          // lh
                #pragma unroll
                for (int nf = 0; nf < 8; nf++)
                    mma16816(acc[mf][nf], al[mf], bh[nf][0], bh[nf][1]);
            #pragma unroll
            for (int nf2 = 0; nf2 < 4; nf2++) {
                uint32_t r0, r1, r2, r3;
                uint32_t bd = sptr(Blb + (ks * 16 + lrow) * BSTR + wn + nf2 * 16 + lcol8);
                LDSM4T(r0, r1, r2, r3, bd);
                bl[2 * nf2][0] = r0;     bl[2 * nf2][1] = r1;
                bl[2 * nf2 + 1][0] = r2; bl[2 * nf2 + 1][1] = r3;
            }
            #pragma unroll
            for (int mf = 0; mf < 2; mf++)          // hl
                #pragma unroll
                for (int nf = 0; nf < 8; nf++)
                    mma16816(acc[mf][nf], ah[mf], bl[nf][0], bl[nf][1]);
        }
        __syncthreads();
        if (kt + 2 < KT) { issue((kt + 2) % 3, (kt + 2) * 32); CPCOMMIT(); }
    }

    // epilogue
    const int g = lane >> 2, tg = lane & 3;
    #pragma unroll
    for (int mf = 0; mf < 2; mf++) {
        #pragma unroll
        for (int nf = 0; nf < 8; nf++) {
            const int col = n0 + wn + nf * 8 + 2 * tg;
            #pragma unroll
            for (int half = 0; half < 2; half++) {
                const int row = m0 + wm + mf * 16 + g + half * 8;
                float vx = acc[mf][nf][half * 2], vy = acc[mf][nf][half * 2 + 1];
                if (MODE == 1) {
                    const int which = col / Hh;
                    const int rem = col - which * Hh;
                    const int head = rem >> 6, d0 = rem & 63;
                    const int bb = row >> 11, ss = row & (Ss - 1);
                    const size_t off =
                        ((((size_t)which * Bb + bb) * NH + head) * Ss + ss) * HD + d0;
                    uint32_t hi, lo;
                    split2(vx, vy, hi, lo);
                    *(uint32_t*)(g_qkvh + off) = hi;
                    *(uint32_t*)(g_qkvl + off) = lo;
                } else {
                    *(float2*)(C + (size_t)row * N + col) = make_float2(vx, vy);
                }
            }
        }
    }
}

// ---------------------------------------------------------------------------
// Flash attention, bf16 hi/lo, 128 q-rows, 4 warps, KV tile 64,
// cp.async double-buffered, cross-pass operand reuse, exp2-domain softmax.
// ---------------------------------------------------------------------------
#define QSTR 72
#define ATTN_SMEM ((2 * 128 * QSTR + 8 * 64 * QSTR) * 2)  // bytes
#define SCL 0.18033688011112042f   // 0.125 * log2(e)

__global__ void __launch_bounds__(128, 2)
attn_bf()
{
    extern __shared__ __align__(16) __nv_bfloat16 sma[];
    __nv_bfloat16* Qhi = sma;
    __nv_bfloat16* Qlo = Qhi + 128 * QSTR;
    __nv_bfloat16* Khs = Qlo + 128 * QSTR;
    __nv_bfloat16* Kls = Khs + 2 * 64 * QSTR;
    __nv_bfloat16* Vhs = Kls + 2 * 64 * QSTR;
    __nv_bfloat16* Vls = Vhs + 2 * 64 * QSTR;

    const int t = threadIdx.x;
    const int lane = t & 31, warp = t >> 5;
    const int iq = blockIdx.x, h = blockIdx.y, b = blockIdx.z;
    const int wm = warp * 32;
    const int g = lane >> 2, tg = lane & 3;
    const int lrow = (lane & 7) + ((lane >> 3) & 1) * 8;
    const int lcol8 = (lane >> 4) * 8;

    const size_t head_off = (((size_t)b * NH) + h) * (size_t)Ss * HD;
    const size_t plane = (size_t)Bb * NH * Ss * HD;
    const __nv_bfloat16* Qgh = g_qkvh + head_off + (size_t)iq * 128 * HD;
    const __nv_bfloat16* Qgl = g_qkvl + head_off + (size_t)iq * 128 * HD;
    const __nv_bfloat16* Kgh = g_qkvh + plane + head_off;
    const __nv_bfloat16* Kgl = g_qkvl + plane + head_off;
    const __nv_bfloat16* Vgh = g_qkvh + 2 * plane + head_off;
    const __nv_bfloat16* Vgl = g_qkvl + 2 * plane + head_off;

    auto issue_kv = [&](int jt, int stg) {
        #pragma unroll
        for (int i = 0; i < 4; i++) {
            int c = t + i * 128;
            int row = c >> 3, co = (c & 7) * 8;
            size_t src = (size_t)(jt * 64 + row) * HD + co;
            uint32_t doff = stg * 64 * QSTR + row * QSTR + co;
            CPA(sptr(Khs + doff), Kgh + src);
            CPA(sptr(Kls + doff), Kgl + src);
            CPA(sptr(Vhs + doff), Vgh + src);
            CPA(sptr(Vls + doff), Vgl + src);
        }
    };

    int st = 0;
    issue_kv(0, 0);
    CPCOMMIT();

    #pragma unroll
    for (int i = 0; i < 8; i++) {
        *(uint4*)(Qhi + t * QSTR + i * 8) = *(const uint4*)(Qgh + t * HD + i * 8);
        *(uint4*)(Qlo + t * QSTR + i * 8) = *(const uint4*)(Qgl + t * HD + i * 8);
    }

    float o[2][8][4] = {};
    float mi[4], li[4];
    #pragma unroll
    for (int i = 0; i < 4; i++) { mi[i] = -1e30f; li[i] = 0.f; }

    const int njt = 2 * iq + 2;
    for (int jt = 0; jt < njt; jt++) {
        if (jt + 1 < njt) { issue_kv(jt + 1, st ^ 1); CPCOMMIT(); CPWAIT1(); }
        else              { CPWAIT0(); }
        __syncthreads();

        const __nv_bfloat16* Khb = Khs + st * 64 * QSTR;
        const __nv_bfloat16* Klb = Kls + st * 64 * QSTR;
        const __nv_bfloat16* Vhb = Vhs + st * 64 * QSTR;
        const __nv_bfloat16* Vlb = Vls + st * 64 * QSTR;

        // ---- S = Q @ K^T with reuse: hh, lh, hl per ks ----
        float s[2][8][4] = {};
        #pragma unroll
        for (int ks = 0; ks < 4; ks++) {
            uint32_t qh[2][4], ql[2][4], kh[8][2], kl[8][2];
            #pragma unroll
            for (int mf = 0; mf < 2; mf++) {
                uint32_t ad = sptr(Qhi + (wm + mf * 16 + lrow) * QSTR + ks * 16 + lcol8);
                LDSM4(qh[mf][0], qh[mf][1], qh[mf][2], qh[mf][3], ad);
            }
            #pragma unroll
            for (int kf2 = 0; kf2 < 4; kf2++) {
                uint32_t r0, r1, r2, r3;
                uint32_t bd = sptr(Khb + (kf2 * 16 + (lane >> 4) * 8 + (lane & 7)) * QSTR +
                                   ks * 16 + ((lane >> 3) & 1) * 8);
                LDSM4(r0, r1, r2, r3, bd);
                kh[2 * kf2][0] = r0;     kh[2 * kf2][1] = r1;
                kh[2 * kf2 + 1][0] = r2; kh[2 * kf2 + 1][1] = r3;
            }
            #pragma unroll
            for (int mf = 0; mf < 2; mf++)
                #pragma unroll
                for (int nf = 0; nf < 8; nf++)
                    mma16816(s[mf][nf], qh[mf], kh[nf][0], kh[nf][1]);
            #pragma unroll
            for (int mf = 0; mf < 2; mf++) {
                uint32_t ad = sptr(Qlo + (wm + mf * 16 + lrow) * QSTR + ks * 16 + lcol8);
                LDSM4(ql[mf][0], ql[mf][1], ql[mf][2], ql[mf][3], ad);
            }
            #pragma unroll
            for (int mf = 0; mf < 2; mf++)
                #pragma unroll
                for (int nf = 0; nf < 8; nf++)
                    mma16816(s[mf][nf], ql[mf], kh[nf][0], kh[nf][1]);
            #pragma unroll
            for (int kf2 = 0; kf2 < 4; kf2++) {
                uint32_t r0, r1, r2, r3;
                uint32_t bd = sptr(Klb + (kf2 * 16 + (lane >> 4) * 8 + (lane & 7)) * QSTR +
                                   ks * 16 + ((lane >> 3) & 1) * 8);
                LDSM4(r0, r1, r2, r3, bd);
                kl[2 * kf2][0] = r0;     kl[2 * kf2][1] = r1;
                kl[2 * kf2 + 1][0] = r2; kl[2 * kf2 + 1][1] = r3;
            }
            #pragma unroll
            for (int mf = 0; mf < 2; mf++)
                #pragma unroll
                for (int nf = 0; nf < 8; nf++)
                    mma16816(s[mf][nf], qh[mf], kl[nf][0], kl[nf][1]);
        }

        // ---- scale to exp2 domain, mask, online softmax ----
        #pragma unroll
        for (int mf = 0; mf < 2; mf++)
            #pragma unroll
            for (int nf = 0; nf < 8; nf++)
                #pragma unroll
                for (int c = 0; c < 4; c++)
                    s[mf][nf][c] *= SCL;

        if (jt >= 2 * iq) {
            #pragma unroll
            for (int mf = 0; mf < 2; mf++)
                #pragma unroll
                for (int nf = 0; nf < 8; nf++)
                    #pragma unroll
                    for (int c = 0; c < 4; c++) {
                        int q = iq * 128 + wm + mf * 16 + g + (c >> 1) * 8;
                        int col = jt * 64 + nf * 8 + 2 * tg + (c & 1);
                        if (col > q) s[mf][nf][c] = -1e30f;
                    }
        }

        float fs[4];
        #pragma unroll
        for (int mf = 0; mf < 2; mf++) {
            #pragma unroll
            for (int half = 0; half < 2; half++) {
                const int ri = mf * 2 + half;
                float mt = -1e30f;
                #pragma unroll
                for (int nf = 0; nf < 8; nf++) {
                    mt = fmaxf(mt, s[mf][nf][half * 2]);
                    mt = fmaxf(mt, s[mf][nf][half * 2 + 1]);
                }
                mt = fmaxf(mt, __shfl_xor_sync(0xffffffffu, mt, 1));
                mt = fmaxf(mt, __shfl_xor_sync(0xffffffffu, mt, 2));
                float mn = fmaxf(mi[ri], mt);
                float f = exp2f(mi[ri] - mn);
                float rs = 0.f;
                #pragma unroll
                for (int nf = 0; nf < 8; nf++) {
                    float e0 = exp2f(s[mf][nf][half * 2] - mn);
                    float e1 = exp2f(s[mf][nf][half * 2 + 1] - mn);
                    s[mf][nf][half * 2] = e0;
                    s[mf][nf][half * 2 + 1] = e1;
                    rs += e0 + e1;
                }
                rs += __shfl_xor_sync(0xffffffffu, rs, 1);
                rs += __shfl_xor_sync(0xffffffffu, rs, 2);
                li[ri] = li[ri] * f + rs;
                mi[ri] = mn;
                fs[ri] = f;
            }
        }
        #pragma unroll
        for (int mf = 0; mf < 2; mf++)
            #pragma unroll
            for (int nf = 0; nf < 8; nf++)
                #pragma unroll
                for (int c = 0; c < 4; c++)
                    o[mf][nf][c] *= fs[mf * 2 + (c >> 1)];

        // ---- O += P @ V with reuse: PhVh, PlVh, PhVl per ks ----
        #pragma unroll
        for (int ks = 0; ks < 4; ks++) {
            uint32_t ph[2][4], pl[2][4], vh[8][2], vl[8][2];
            #pragma unroll
            for (int mf = 0; mf < 2; mf++) {
                const float* c0 = s[mf][2 * ks];
                const float* c1 = s[mf][2 * ks + 1];
                ph[mf][0] = packbf(c0[0], c0[1]);
                ph[mf][1] = packbf(c0[2], c0[3]);
                ph[mf][2] = packbf(c1[0], c1[1]);
                ph[mf][3] = packbf(c1[2], c1[3]);
                float2 hf;
                hf = unpackbf(ph[mf][0]);
                pl[mf][0] = packbf(c0[0] - hf.x, c0[1] - hf.y);
                hf = unpackbf(ph[mf][1]);
                pl[mf][1] = packbf(c0[2] - hf.x, c0[3] - hf.y);
                hf = unpackbf(ph[mf][2]);
                pl[mf][2] = packbf(c1[0] - hf.x, c1[1] - hf.y);
                hf = unpackbf(ph[mf][3]);
                pl[mf][3] = packbf(c1[2] - hf.x, c1[3] - hf.y);
            }
            #pragma unroll
            for (int df2 = 0; df2 < 4; df2++) {
                uint32_t r0, r1, r2, r3;
                uint32_t bd = sptr(Vhb + (ks * 16 + lrow) * QSTR + df2 * 16 + lcol8);
                LDSM4T(r0, r1, r2, r3, bd);
                vh[2 * df2][0] = r0;     vh[2 * df2][1] = r1;
                vh[2 * df2 + 1][0] = r2; vh[2 * df2 + 1][1] = r3;
            }
            #pragma unroll
            for (int mf = 0; mf < 2; mf++)
                #pragma unroll
                for (int nf = 0; nf < 8; nf++)
                    mma16816(o[mf][nf], ph[mf], vh[nf][0], vh[nf][1]);
            #pragma unroll
            for (int mf = 0; mf < 2; mf++)
                #pragma unroll
                for (int nf = 0; nf < 8; nf++)
                    mma16816(o[mf][nf], pl[mf], vh[nf][0], vh[nf][1]);
            #pragma unroll
            for (int df2 = 0; df2 < 4; df2++) {
                uint32_t r0, r1, r2, r3;
                uint32_t bd = sptr(Vlb + (ks * 16 + lrow) * QSTR + df2 * 16 + lcol8);
                LDSM4T(r0, r1, r2, r3, bd);
                vl[2 * df2][0] = r0;     vl[2 * df2][1] = r1;
                vl[2 * df2 + 1][0] = r2; vl[2 * df2 + 1][1] = r3;
            }
            #pragma unroll
            for (int mf = 0; mf < 2; mf++)
                #pragma unroll
                for (int nf = 0; nf < 8; nf++)
                    mma16816(o[mf][nf], ph[mf], vl[nf][0], vl[nf][1]);
        }
        __syncthreads();
        st ^= 1;
    }

    // epilogue: normalize, write ctx hi/lo bf16 [b][s][h*64+d]
    #pragma unroll
    for (int mf = 0; mf < 2; mf++) {
        #pragma unroll
        for (int half = 0; half < 2; half++) {
            const int ri = mf * 2 + half;
            const float inv = 1.0f / li[ri];
            const int row = iq * 128 + wm + mf * 16 + g + half * 8;
            #pragma unroll
            for (int nf = 0; nf < 8; nf++) {
                const int col = nf * 8 + 2 * tg;
                const size_t off = ((size_t)b * Ss + row) * Hh + h * HD + col;
                uint32_t hi, lo;
                split2(o[mf][nf][half * 2] * inv, o[mf][nf][half * 2 + 1] * inv,
                       hi, lo);
                *(uint32_t*)(g_ctxh + off) = hi;
                *(uint32_t*)(g_ctxl + off) = lo;
            }
        }
    }
}

// ---------------------------------------------------------------------------

extern "C" void kernel_launch(void* const* d_in, const int* in_sizes, int n_in,
                              void* d_out, int out_size)
{
    const float* x    = (const float*)d_in[0];   // [4,2048,768]
    const float* wqkv = (const float*)d_in[1];   // [768,2304]
    const float* wout = (const float*)d_in[2];   // [768,768]
    float* out = (float*)d_out;                  // [4,2048,768]

    __nv_bfloat16 *xh, *xl, *wqh, *wql, *woh, *wol, *ch, *cl;
    cudaGetSymbolAddress((void**)&xh,  g_xh);
    cudaGetSymbolAddress((void**)&xl,  g_xl);
    cudaGetSymbolAddress((void**)&wqh, g_wqh);
    cudaGetSymbolAddress((void**)&wql, g_wql);
    cudaGetSymbolAddress((void**)&woh, g_woh);
    cudaGetSymbolAddress((void**)&wol, g_wol);
    cudaGetSymbolAddress((void**)&ch,  g_ctxh);
    cudaGetSymbolAddress((void**)&cl,  g_ctxl);

    // 0) convert inputs to bf16 hi/lo
    cvt_kernel<<<(Bb * Ss * Hh / 4 + 255) / 256, 256>>>(x, xh, xl, Bb * Ss * Hh);
    cvt_kernel<<<(Hh * 3 * Hh / 4 + 255) / 256, 256>>>(wqkv, wqh, wql, Hh * 3 * Hh);
    cvt_kernel<<<(Hh * Hh / 4 + 255) / 256, 256>>>(wout, woh, wol, Hh * Hh);

    // 1) QKV projection (scatter into g_qkvh/l)
    cudaFuncSetAttribute(gemm_bf<1>,
                         cudaFuncAttributeMaxDynamicSharedMemorySize, GEMM_SMEM);
    gemm_bf<1><<<dim3(2304 / 128, 8192 / 128), 256, GEMM_SMEM>>>(
        xh, xl, wqh, wql, nullptr, Bb * Ss, 3 * Hh, Hh);

    // 2) Flash attention (causal)
    cudaFuncSetAttribute(attn_bf,
                         cudaFuncAttributeMaxDynamicSharedMemorySize, ATTN_SMEM);
    attn_bf<<<dim3(Ss / 128, NH, Bb), 128, ATTN_SMEM>>>();

    // 3) Output projection
    cudaFuncSetAttribute(gemm_bf<2>,
                         cudaFuncAttributeMaxDynamicSharedMemorySize, GEMM_SMEM);
    gemm_bf<2><<<dim3(768 / 128, 8192 / 128), 256, GEMM_SMEM>>>(
        ch, cl, woh, wol, out, Bb * Ss, Hh, Hh);
}